// round 16
// baseline (speedup 1.0000x reference)
#include <cuda_runtime.h>
#include <cuda_fp16.h>
#include <cstdint>

// ---------------------------------------------------------------- constants
#define D_Z     1024
#define D_MODEL 4096
#define M_ROWS  16384
#define EPS     1e-5f

#define BM 128
#define BN 128
#define NKB (D_Z / 16)          // 64 k-blocks of 16

#define LN_BLOCKS 1024           // 16 rows per block -> one mblk each
#define W_BLOCKS  1024           // 64x64 tiles: (4096/64)*(1024/64)

// fragment-major scratch: block (xblk, kblk) = 32 lanes x 16B = 512B
// index (uint4): (xblk*64 + kblk)*32 + lane
__device__ uint4 g_znf[(size_t)(M_ROWS / 16) * NKB * 32];   // 32 MB
__device__ uint4 g_wbf[(size_t)(D_MODEL / 16) * NKB * 32];  // 8 MB

// ---------------------------------------------------------------- K1: prep
// blocks [0,1024): LayerNorm 16 rows -> fragment-major A
// blocks [1024,2048): W fp32 -> fp16 fragment-major B (64n x 64k tile each)
__global__ __launch_bounds__(256) void prep_kernel(const float* __restrict__ z,
                                                   const float* __restrict__ gamma,
                                                   const float* __restrict__ beta,
                                                   const float* __restrict__ W) {
    __shared__ uint32_t st[16 * 516];          // 33 KB, reused by both paths
    int blk  = blockIdx.x;
    int tid  = threadIdx.x;
    int wid  = tid >> 5;
    int lane = tid & 31;

    if (blk < LN_BLOCKS) {
        // ---- LayerNorm: 8 warps x 2 rows, stage halves into st[row][516 words]
        #pragma unroll
        for (int rr = 0; rr < 2; rr++) {
            int row_l = wid * 2 + rr;
            int row   = blk * 16 + row_l;
            const float4* zp = (const float4*)(z + (size_t)row * D_Z);
            float4 v[8];
            #pragma unroll
            for (int c = 0; c < 8; c++) v[c] = zp[lane + c * 32];

            float s = 0.f, ss = 0.f;
            #pragma unroll
            for (int c = 0; c < 8; c++) {
                s  += v[c].x + v[c].y + v[c].z + v[c].w;
                ss += v[c].x * v[c].x + v[c].y * v[c].y + v[c].z * v[c].z + v[c].w * v[c].w;
            }
            #pragma unroll
            for (int o = 16; o > 0; o >>= 1) {
                s  += __shfl_xor_sync(0xffffffffu, s, o);
                ss += __shfl_xor_sync(0xffffffffu, ss, o);
            }
            float mu   = s * (1.0f / D_Z);
            float var  = ss * (1.0f / D_Z) - mu * mu;
            float rstd = rsqrtf(var + EPS);

            const float4* gp = (const float4*)gamma;
            const float4* bp = (const float4*)beta;
            #pragma unroll
            for (int c = 0; c < 8; c++) {
                float4 g = gp[lane + c * 32];
                float4 b = bp[lane + c * 32];
                float o0 = (v[c].x - mu) * rstd * g.x + b.x;
                float o1 = (v[c].y - mu) * rstd * g.y + b.y;
                float o2 = (v[c].z - mu) * rstd * g.z + b.z;
                float o3 = (v[c].w - mu) * rstd * g.w + b.w;
                __half2 h0 = __floats2half2_rn(o0, o1);
                __half2 h1 = __floats2half2_rn(o2, o3);
                int w = c * 64 + lane * 2;             // word = k/2
                st[row_l * 516 + w]     = *(uint32_t*)&h0;
                st[row_l * 516 + w + 1] = *(uint32_t*)&h1;
            }
        }
        __syncthreads();

        // ---- pack: 64 kblk x 32 lanes, 8 chunks per thread
        int l4 = lane & 3, r = lane >> 2;
        #pragma unroll
        for (int it = 0; it < 8; it++) {
            int kblk = (tid >> 5) + it * 8;
            int w = kblk * 8 + l4;
            uint4 o;
            o.x = st[r * 516 + w];
            o.y = st[(r + 8) * 516 + w];
            o.z = st[r * 516 + w + 4];
            o.w = st[(r + 8) * 516 + w + 4];
            g_znf[((size_t)blk * NKB + kblk) * 32 + lane] = o;
        }
    } else {
        // ---- W tile: 64 n x 64 k; stage s16[n][k] pitch 74 halves (37 words)
        int wb = blk - LN_BLOCKS;
        int n0 = (wb & 63) * 64;
        int k0 = (wb >> 6) * 64;
        __half* sh = (__half*)st;

        int nl = tid & 63;
        #pragma unroll
        for (int p = 0; p < 16; p++) {
            int kl = p * 4 + (tid >> 6);
            float w = W[(size_t)(k0 + kl) * D_MODEL + n0 + nl];
            sh[nl * 74 + kl] = __float2half(w);
        }
        __syncthreads();

        // pack: 4 nblk x 4 kblk x 32 lanes = 512 chunks, 2 per thread
        int l4 = lane & 3;
        #pragma unroll
        for (int it = 0; it < 2; it++) {
            int c   = tid + it * 256;
            int ln  = c & 31;
            int kb2 = (c >> 5) & 3;
            int nb2 = c >> 7;
            int l4c = ln & 3;
            int nr  = nb2 * 16 + (ln >> 2);
            uint4 o;
            o.x = st[nr * 37 + kb2 * 8 + l4c];
            o.y = st[nr * 37 + kb2 * 8 + l4c + 4];
            o.z = st[(nr + 8) * 37 + kb2 * 8 + l4c];
            o.w = st[(nr + 8) * 37 + kb2 * 8 + l4c + 4];
            int nblk = (n0 >> 4) + nb2;
            int kblk = (k0 >> 4) + kb2;
            g_wbf[((size_t)nblk * NKB + kblk) * 32 + ln] = o;
        }
        (void)l4;
    }
}

// ---------------------------------------------------------------- PTX wrappers
__device__ __forceinline__ void mma_16816(float c[4], const uint32_t a[4],
                                          uint32_t b0, uint32_t b1) {
    asm volatile("mma.sync.aligned.m16n8k16.row.col.f32.f16.f16.f32 "
                 "{%0,%1,%2,%3}, {%4,%5,%6,%7}, {%8,%9}, {%0,%1,%2,%3};\n"
                 : "+f"(c[0]), "+f"(c[1]), "+f"(c[2]), "+f"(c[3])
                 : "r"(a[0]), "r"(a[1]), "r"(a[2]), "r"(a[3]), "r"(b0), "r"(b1));
}

// fast tanh: tanh(t) = 1 - 2/(exp(2t)+1), rel err ~1e-6
__device__ __forceinline__ float fast_tanh3(float x, float sc3) {
    float t = x * sc3;
    float e;
    asm("ex2.approx.f32 %0, %1;" : "=f"(e) : "f"(t * 2.885390082f));
    float r;
    asm("rcp.approx.f32 %0, %1;" : "=f"(r) : "f"(e + 1.0f));
    return 3.0f * (1.0f - 2.0f * r);
}

// ---------------------------------------------------------------- K2: GEMM
// 128 threads = 4 warps (2x2), warp tile 64x64; NO shared memory, NO barriers.
// Operands fetched fragment-major via LDG.128, triple-buffered, prefetch dist 2.
#define PF(buf, Ak, Bk)                                                         \
    do {                                                                        \
        _Pragma("unroll")                                                       \
        for (int mi = 0; mi < 4; mi++) af[buf][mi] = __ldg(&(Ak)[mi * (NKB*32)]); \
        _Pragma("unroll")                                                       \
        for (int ni = 0; ni < 4; ni++) bf[buf][ni] = __ldg(&(Bk)[ni * (NKB*32)]); \
        (Ak) += 32; (Bk) += 32;                                                 \
    } while (0)

#define MMA_G(buf)                                                              \
    do {                                                                        \
        _Pragma("unroll")                                                       \
        for (int mi = 0; mi < 4; mi++) {                                        \
            const uint32_t* a = (const uint32_t*)&af[buf][mi];                  \
            _Pragma("unroll")                                                   \
            for (int ni = 0; ni < 4; ni++) {                                    \
                mma_16816(acc[mi][ni * 2 + 0], a, bf[buf][ni].x, bf[buf][ni].y);\
                mma_16816(acc[mi][ni * 2 + 1], a, bf[buf][ni].z, bf[buf][ni].w);\
            }                                                                   \
        }                                                                       \
    } while (0)

__global__ __launch_bounds__(128, 2) void gemm_kernel(const float* __restrict__ bias,
                                                      const float* __restrict__ scale,
                                                      float* __restrict__ out) {
    int tid  = threadIdx.x;
    int wid  = tid >> 5;
    int lane = tid & 31;
    int wm   = wid >> 1;        // 0..1 (64 rows)
    int wn   = wid & 1;         // 0..1 (64 cols)
    int bm   = blockIdx.y;
    int bn   = blockIdx.x;

    float acc[4][8][4];
    #pragma unroll
    for (int i = 0; i < 4; i++)
        #pragma unroll
        for (int j = 0; j < 8; j++)
            #pragma unroll
            for (int k = 0; k < 4; k++) acc[i][j][k] = 0.f;

    const uint4* Ak = g_znf + ((size_t)(bm * 8 + wm * 4) * NKB) * 32 + lane;
    const uint4* Bk = g_wbf + ((size_t)(bn * 8 + wn * 4) * NKB) * 32 + lane;

    uint4 af[3][4], bf[3][4];

    PF(0, Ak, Bk);              // kb 0
    PF(1, Ak, Bk);              // kb 1

    for (int i = 0; i < 20; i++) {
        PF(2, Ak, Bk);  MMA_G(0);      // pf kb=3i+2, mma 3i
        PF(0, Ak, Bk);  MMA_G(1);      // pf 3i+3,   mma 3i+1
        PF(1, Ak, Bk);  MMA_G(2);      // pf 3i+4,   mma 3i+2
    }
    // tail: buffers hold kb 60 (buf0), 61 (buf1)
    PF(2, Ak, Bk);  MMA_G(0);          // pf 62, mma 60
    PF(0, Ak, Bk);  MMA_G(1);          // pf 63, mma 61
    MMA_G(2);                          // mma 62
    MMA_G(0);                          // mma 63

    // ---- epilogue: out = 3*tanh((acc + bias)*scale/3)
    float sc3 = scale[0] * (1.0f / 3.0f);
    int rr = lane >> 2;
    int cq = (lane & 3) * 2;

    #pragma unroll
    for (int nb = 0; nb < 8; nb++) {
        int col = bn * BN + wn * 64 + nb * 8 + cq;
        float2 bv = *(const float2*)(bias + col);
        #pragma unroll
        for (int mi = 0; mi < 4; mi++) {
            int row = bm * BM + wm * 64 + mi * 16 + rr;
            float2 o0, o1;
            o0.x = fast_tanh3(acc[mi][nb][0] + bv.x, sc3);
            o0.y = fast_tanh3(acc[mi][nb][1] + bv.y, sc3);
            o1.x = fast_tanh3(acc[mi][nb][2] + bv.x, sc3);
            o1.y = fast_tanh3(acc[mi][nb][3] + bv.y, sc3);
            *(float2*)(out + (size_t)row * D_MODEL + col)       = o0;
            *(float2*)(out + (size_t)(row + 8) * D_MODEL + col) = o1;
        }
    }
}

// ---------------------------------------------------------------- launch
extern "C" void kernel_launch(void* const* d_in, const int* in_sizes, int n_in,
                              void* d_out, int out_size) {
    const float* z     = (const float*)d_in[0];
    const float* gamma = (const float*)d_in[1];
    const float* beta  = (const float*)d_in[2];
    const float* W     = (const float*)d_in[3];
    const float* b     = (const float*)d_in[4];
    const float* scale = (const float*)d_in[5];
    float* out = (float*)d_out;
    (void)in_sizes; (void)n_in; (void)out_size;

    prep_kernel<<<LN_BLOCKS + W_BLOCKS, 256>>>(z, gamma, beta, W);
    dim3 grid(D_MODEL / BN, M_ROWS / BM);   // (32, 128) = 4096 CTAs, 2/SM
    gemm_kernel<<<grid, 128>>>(b, scale, out);
}

// round 17
// speedup vs baseline: 1.4518x; 1.4518x over previous
#include <cuda_runtime.h>
#include <cuda_fp16.h>
#include <cstdint>

// ---------------------------------------------------------------- constants
#define D_Z     1024
#define D_MODEL 4096
#define M_ROWS  16384
#define EPS     1e-5f

#define BM 128
#define BN 128
#define BK 64
#define KITERS (D_Z / BK)      // 16
#define STAGES 3

#define LDA 72                  // 64 + 8 pad (fp16): conflict-free ldmatrix
#define LDB 136                 // 128 + 8 pad
#define A_STAGE_B (BM * LDA * 2)          // 18432 B
#define B_STAGE_B (BK * LDB * 2)          // 17408 B
#define STAGE_B   (A_STAGE_B + B_STAGE_B) // 35840 B
#define SMEM_TOTAL (STAGES * STAGE_B)     // 107520 B -> 2 CTAs/SM

#define LN_BLOCKS   (M_ROWS / 8)          // 2048 (8 rows per block)
#define WCONV_BLOCKS 1024

// scratch (allocation-free rule: device globals)
__device__ __half g_zn[(size_t)M_ROWS * D_Z];     // LN output fp16 [M,K]
__device__ __half g_wb[(size_t)D_Z * D_MODEL];    // W fp16 [K,N]

// ---------------------------------------------------------------- K1: merged prep
__global__ __launch_bounds__(256) void prep_kernel(const float* __restrict__ z,
                                                   const float* __restrict__ gamma,
                                                   const float* __restrict__ beta,
                                                   const float* __restrict__ W) {
    int blk = blockIdx.x;
    int t   = threadIdx.x;

    if (blk >= LN_BLOCKS) {
        size_t base = (size_t)(blk - LN_BLOCKS) * 1024 + t;
        __half2* dst = (__half2*)g_wb;
        #pragma unroll
        for (int u = 0; u < 4; u++) {
            size_t i = base + (size_t)u * 256;
            float4 v = ((const float4*)W)[i];
            dst[i * 2 + 0] = __floats2half2_rn(v.x, v.y);
            dst[i * 2 + 1] = __floats2half2_rn(v.z, v.w);
        }
        return;
    }

    // ---- warp-per-row LayerNorm (no block barriers)
    int wid  = t >> 5;
    int lane = t & 31;
    int row  = blk * 8 + wid;

    const float4* zp = (const float4*)(z + (size_t)row * D_Z);
    float4 v[8];
    #pragma unroll
    for (int c = 0; c < 8; c++) v[c] = zp[lane + c * 32];

    float s = 0.f, ss = 0.f;
    #pragma unroll
    for (int c = 0; c < 8; c++) {
        s  += v[c].x + v[c].y + v[c].z + v[c].w;
        ss += v[c].x * v[c].x + v[c].y * v[c].y + v[c].z * v[c].z + v[c].w * v[c].w;
    }
    #pragma unroll
    for (int o = 16; o > 0; o >>= 1) {
        s  += __shfl_xor_sync(0xffffffffu, s, o);
        ss += __shfl_xor_sync(0xffffffffu, ss, o);
    }
    float mu   = s * (1.0f / D_Z);
    float var  = ss * (1.0f / D_Z) - mu * mu;
    float rstd = rsqrtf(var + EPS);

    const float4* gp = (const float4*)gamma;
    const float4* bp = (const float4*)beta;
    uint2* dst = (uint2*)(g_zn + (size_t)row * D_Z);
    #pragma unroll
    for (int c = 0; c < 8; c++) {
        float4 g = gp[lane + c * 32];
        float4 b = bp[lane + c * 32];
        float o0 = (v[c].x - mu) * rstd * g.x + b.x;
        float o1 = (v[c].y - mu) * rstd * g.y + b.y;
        float o2 = (v[c].z - mu) * rstd * g.z + b.z;
        float o3 = (v[c].w - mu) * rstd * g.w + b.w;
        __half2 h0 = __floats2half2_rn(o0, o1);
        __half2 h1 = __floats2half2_rn(o2, o3);
        uint2 pack;
        pack.x = *(uint32_t*)&h0;
        pack.y = *(uint32_t*)&h1;
        dst[lane + c * 32] = pack;
    }
}

// ---------------------------------------------------------------- PTX wrappers
__device__ __forceinline__ void ldmatrix_x4(uint32_t r[4], uint32_t addr) {
    asm volatile("ldmatrix.sync.aligned.m8n8.x4.shared.b16 {%0,%1,%2,%3}, [%4];\n"
                 : "=r"(r[0]), "=r"(r[1]), "=r"(r[2]), "=r"(r[3]) : "r"(addr));
}
__device__ __forceinline__ void ldmatrix_b(uint32_t& b00, uint32_t& b01,
                                           uint32_t& b10, uint32_t& b11, uint32_t addr) {
    asm volatile("ldmatrix.sync.aligned.m8n8.x4.trans.shared.b16 {%0,%1,%2,%3}, [%4];\n"
                 : "=r"(b00), "=r"(b01), "=r"(b10), "=r"(b11) : "r"(addr));
}
__device__ __forceinline__ void mma_16816(float c[4], const uint32_t a[4],
                                          uint32_t b0, uint32_t b1) {
    asm volatile("mma.sync.aligned.m16n8k16.row.col.f32.f16.f16.f32 "
                 "{%0,%1,%2,%3}, {%4,%5,%6,%7}, {%8,%9}, {%0,%1,%2,%3};\n"
                 : "+f"(c[0]), "+f"(c[1]), "+f"(c[2]), "+f"(c[3])
                 : "r"(a[0]), "r"(a[1]), "r"(a[2]), "r"(a[3]), "r"(b0), "r"(b1));
}
__device__ __forceinline__ void cp_async16(uint32_t dst, const void* src) {
    asm volatile("cp.async.cg.shared.global [%0], [%1], 16;\n" :: "r"(dst), "l"(src) : "memory");
}
__device__ __forceinline__ void stg_cs_f2(float* p, float2 v) {
    asm volatile("st.global.cs.v2.f32 [%0], {%1, %2};\n" :: "l"(p), "f"(v.x), "f"(v.y) : "memory");
}
#define CP_COMMIT() asm volatile("cp.async.commit_group;" ::: "memory")
#define CP_WAIT1()  asm volatile("cp.async.wait_group 1;" ::: "memory")

// fast tanh: tanh(t) = 1 - 2/(exp(2t)+1), rel err ~1e-6
__device__ __forceinline__ float fast_tanh3(float x, float sc3) {
    float t = x * sc3;
    float e;
    asm("ex2.approx.f32 %0, %1;" : "=f"(e) : "f"(t * 2.885390082f));
    float r;
    asm("rcp.approx.f32 %0, %1;" : "=f"(r) : "f"(e + 1.0f));
    return 3.0f * (1.0f - 2.0f * r);
}

// ---------------------------------------------------------------- K2: GEMM
__device__ __forceinline__ void load_frags(uint32_t base, uint32_t af[4][4], uint32_t bf[16],
                                           const uint32_t aoff[4], const uint32_t boff[4],
                                           uint32_t ko2, uint32_t kb) {
    #pragma unroll
    for (int mi = 0; mi < 4; mi++) ldmatrix_x4(af[mi], base + aoff[mi] + ko2);
    #pragma unroll
    for (int ni = 0; ni < 4; ni++)
        ldmatrix_b(bf[ni * 4 + 0], bf[ni * 4 + 1], bf[ni * 4 + 2], bf[ni * 4 + 3],
                   base + boff[ni] + kb);
}

__global__ __launch_bounds__(128, 2) void gemm_kernel(const float* __restrict__ bias,
                                                      const float* __restrict__ scale,
                                                      float* __restrict__ out) {
    extern __shared__ __align__(16) char smem[];
    uint32_t sb;
    asm("{ .reg .u64 t; cvta.to.shared.u64 t, %1; cvt.u32.u64 %0, t; }" : "=r"(sb) : "l"(smem));

    int tid  = threadIdx.x;
    int wid  = tid >> 5;
    int lane = tid & 31;
    int wm   = wid >> 1;        // 0..1 (64 rows)
    int wn   = wid & 1;         // 0..1 (64 cols)
    int bm   = blockIdx.y;
    int bn   = blockIdx.x;

    float acc[4][8][4];
    #pragma unroll
    for (int i = 0; i < 4; i++)
        #pragma unroll
        for (int j = 0; j < 8; j++)
            #pragma unroll
            for (int k = 0; k < 4; k++) acc[i][j][k] = 0.f;

    int r8 = lane & 7;
    int q  = lane >> 3;

    uint32_t aoff[4], boff[4];
    #pragma unroll
    for (int mi = 0; mi < 4; mi++)
        aoff[mi] = (uint32_t)((wm * 64 + mi * 16 + r8 + (q & 1) * 8) * LDA + (q >> 1) * 8) * 2;
    #pragma unroll
    for (int ni = 0; ni < 4; ni++)
        boff[ni] = (uint32_t)(((q & 1) * 8 + r8) * LDB + wn * 64 + ni * 16 + (q >> 1) * 8) * 2 + A_STAGE_B;

    uint32_t as_off[8], ag_off[8], bs_off[8], bg_off[8];
    #pragma unroll
    for (int i = 0; i < 8; i++) {
        int chunk = tid + i * 128;
        int arow = chunk >> 3, ac = chunk & 7;
        as_off[i] = (uint32_t)(arow * LDA + ac * 8) * 2;
        ag_off[i] = (uint32_t)arow * (D_Z * 2) + ac * 16;
        int brow = chunk >> 4, bc = chunk & 15;
        bs_off[i] = (uint32_t)(brow * LDB + bc * 8) * 2 + A_STAGE_B;
        bg_off[i] = (uint32_t)brow * (D_MODEL * 2) + bc * 16;
    }

    const char* Abase = (const char*)(g_zn + (size_t)(bm * BM) * D_Z);
    const char* Bbase = (const char*)(g_wb + (size_t)(bn * BN));

    // preload stages 0,1
    {
        #pragma unroll
        for (int i = 0; i < 8; i++) cp_async16(sb + as_off[i], Abase + ag_off[i]);
        #pragma unroll
        for (int i = 0; i < 8; i++) cp_async16(sb + bs_off[i], Bbase + bg_off[i]);
        CP_COMMIT();
        uint32_t s1 = sb + STAGE_B;
        const char* Ag = Abase + BK * 2;
        const char* Bg = Bbase + (size_t)BK * D_MODEL * 2;
        #pragma unroll
        for (int i = 0; i < 8; i++) cp_async16(s1 + as_off[i], Ag + ag_off[i]);
        #pragma unroll
        for (int i = 0; i < 8; i++) cp_async16(s1 + bs_off[i], Bg + bg_off[i]);
        CP_COMMIT();
    }

    const char* Agp = Abase + 2 * BK * 2;
    const char* Bgp = Bbase + (size_t)2 * BK * D_MODEL * 2;

    uint32_t abase = sb;
    const uint32_t send = sb + STAGES * STAGE_B;

    uint32_t af[2][4][4];
    uint32_t bf[2][16];

    // stage 0 ready -> load ks=0 fragments into buf 0
    CP_WAIT1();
    __syncthreads();
    load_frags(abase, af[0], bf[0], aoff, boff, 0, 0);

    for (int kt = 0; kt < KITERS; kt++) {
        bool do_refill = (kt + 2 < KITERS);
        uint32_t p = abase + 2 * STAGE_B;
        uint32_t pbase = (p >= send) ? p - STAGES * STAGE_B : p;

        uint32_t nbase = abase + STAGE_B;
        if (nbase >= send) nbase = sb;

        #pragma unroll
        for (int ks = 0; ks < 4; ks++) {
            int cur = ks & 1;

            // fragment prefetch FIRST (never queued behind cp.async in LSU)
            if (ks < 3) {
                load_frags(abase, af[cur ^ 1], bf[cur ^ 1], aoff, boff,
                           (uint32_t)((ks + 1) * 16) * 2,
                           (uint32_t)((ks + 1) * 16) * (LDB * 2));
            }

            // refill of stage kt+2 spread over ks1..ks3 (ks0 kept load-free)
            if (ks == 1 && do_refill) {
                #pragma unroll
                for (int i = 0; i < 4; i++) cp_async16(pbase + as_off[i], Agp + ag_off[i]);
                #pragma unroll
                for (int i = 0; i < 2; i++) cp_async16(pbase + bs_off[i], Bgp + bg_off[i]);
            }
            if (ks == 2 && do_refill) {
                #pragma unroll
                for (int i = 4; i < 8; i++) cp_async16(pbase + as_off[i], Agp + ag_off[i]);
                #pragma unroll
                for (int i = 2; i < 4; i++) cp_async16(pbase + bs_off[i], Bgp + bg_off[i]);
            }

            if (ks < 3) {
                // full MMA group
                #pragma unroll
                for (int mi = 0; mi < 4; mi++)
                    #pragma unroll
                    for (int nb = 0; nb < 8; nb++)
                        mma_16816(acc[mi][nb], af[cur][mi],
                                  bf[cur][(nb >> 1) * 4 + (nb & 1) * 2],
                                  bf[cur][(nb >> 1) * 4 + (nb & 1) * 2 + 1]);
            } else {
                // last refill chunk + commit (group for stage kt+2, possibly empty)
                if (do_refill) {
                    #pragma unroll
                    for (int i = 4; i < 8; i++) cp_async16(pbase + bs_off[i], Bgp + bg_off[i]);
                }
                CP_COMMIT();

                // first half of ks3 MMAs: keeps tensor pipe fed through the barrier
                #pragma unroll
                for (int mi = 0; mi < 2; mi++)
                    #pragma unroll
                    for (int nb = 0; nb < 8; nb++)
                        mma_16816(acc[mi][nb], af[cur][mi],
                                  bf[cur][(nb >> 1) * 4 + (nb & 1) * 2],
                                  bf[cur][(nb >> 1) * 4 + (nb & 1) * 2 + 1]);

                if (kt + 1 < KITERS) {
                    CP_WAIT1();            // stage kt+1 resident (kt+2 may be in flight)
                    __syncthreads();
                    load_frags(nbase, af[cur ^ 1], bf[cur ^ 1], aoff, boff, 0, 0);
                }

                // second half of ks3 MMAs
                #pragma unroll
                for (int mi = 2; mi < 4; mi++)
                    #pragma unroll
                    for (int nb = 0; nb < 8; nb++)
                        mma_16816(acc[mi][nb], af[cur][mi],
                                  bf[cur][(nb >> 1) * 4 + (nb & 1) * 2],
                                  bf[cur][(nb >> 1) * 4 + (nb & 1) * 2 + 1]);
            }
        }

        if (do_refill) {
            Agp += BK * 2;
            Bgp += (size_t)BK * D_MODEL * 2;
        }
        abase = nbase;
    }

    // epilogue: out = 3*tanh((acc + bias)*scale/3); streaming stores (evict-first)
    float sc3 = scale[0] * (1.0f / 3.0f);
    int rr = lane >> 2;
    int cq = (lane & 3) * 2;

    #pragma unroll
    for (int nb = 0; nb < 8; nb++) {
        int col = bn * BN + wn * 64 + nb * 8 + cq;
        float2 bv = *(const float2*)(bias + col);
        #pragma unroll
        for (int mi = 0; mi < 4; mi++) {
            int row = bm * BM + wm * 64 + mi * 16 + rr;
            float2 o0, o1;
            o0.x = fast_tanh3(acc[mi][nb][0] + bv.x, sc3);
            o0.y = fast_tanh3(acc[mi][nb][1] + bv.y, sc3);
            o1.x = fast_tanh3(acc[mi][nb][2] + bv.x, sc3);
            o1.y = fast_tanh3(acc[mi][nb][3] + bv.y, sc3);
            stg_cs_f2(out + (size_t)row * D_MODEL + col,       o0);
            stg_cs_f2(out + (size_t)(row + 8) * D_MODEL + col, o1);
        }
    }
}

// ---------------------------------------------------------------- launch
extern "C" void kernel_launch(void* const* d_in, const int* in_sizes, int n_in,
                              void* d_out, int out_size) {
    const float* z     = (const float*)d_in[0];
    const float* gamma = (const float*)d_in[1];
    const float* beta  = (const float*)d_in[2];
    const float* W     = (const float*)d_in[3];
    const float* b     = (const float*)d_in[4];
    const float* scale = (const float*)d_in[5];
    float* out = (float*)d_out;
    (void)in_sizes; (void)n_in; (void)out_size;

    cudaFuncSetAttribute(gemm_kernel, cudaFuncAttributeMaxDynamicSharedMemorySize, SMEM_TOTAL);

    prep_kernel<<<LN_BLOCKS + WCONV_BLOCKS, 256>>>(z, gamma, beta, W);
    dim3 grid(D_MODEL / BN, M_ROWS / BM);   // (32, 128) = 4096 CTAs, 2/SM
    gemm_kernel<<<grid, 128, SMEM_TOTAL>>>(b, scale, out);
}